// round 3
// baseline (speedup 1.0000x reference)
#include <cuda_runtime.h>
#include <math.h>

#define N_NODES 8192
#define N_EDGES 65536
#define CDIM 64
#define NB 8
#define NELEM 10
#define NGRAPH 8

// Scratch (device globals; no allocation allowed)
__device__ float g_s[N_NODES * CDIM];      // current h[:,0,:]
__device__ float g_m[N_NODES * CDIM];      // message accumulator
__device__ float g_energy[N_NODES];        // per-node energy
__device__ float g_ef[N_EDGES * NB];       // edge radial features
__device__ int   g_elem[N_NODES];          // element index per node

// ---------------- packed f32x2 helpers (Blackwell FFMA2) -------------------
__device__ __forceinline__ unsigned long long pack2(float x, float y) {
    unsigned long long r;
    asm("mov.b64 %0, {%1, %2};" : "=l"(r) : "f"(x), "f"(y));
    return r;
}
__device__ __forceinline__ unsigned long long ffma2(unsigned long long a,
                                                    unsigned long long b,
                                                    unsigned long long c) {
    unsigned long long d;
    asm("fma.rn.f32x2 %0, %1, %2, %3;" : "=l"(d) : "l"(a), "l"(b), "l"(c));
    return d;
}
__device__ __forceinline__ float2 unpack2(unsigned long long v) {
    float x, y;
    asm("mov.b64 {%0, %1}, %2;" : "=f"(x), "=f"(y) : "l"(v));
    return make_float2(x, y);
}

__device__ __forceinline__ float silu(float x) {
    return __fdividef(x, 1.0f + __expf(-x));
}

// ---------------------------------------------------------------------------
// init: element lookup, s = W_embed[elem], energy = atomic_energies[elem],
// zero m, zero d_out
// ---------------------------------------------------------------------------
__global__ void init_kernel(const float* __restrict__ node_attrs,
                            const float* __restrict__ atomic_energies,
                            const float* __restrict__ W_embed,
                            float* __restrict__ d_out) {
    int n = blockIdx.x * blockDim.x + threadIdx.x;
    if (n >= N_NODES) return;
    if (n < NGRAPH) d_out[n] = 0.0f;

    const float* row = node_attrs + n * NELEM;
    int el = 0;
#pragma unroll
    for (int k = 0; k < NELEM; k++)
        if (row[k] > 0.5f) el = k;
    g_elem[n] = el;
    g_energy[n] = atomic_energies[el];

    const float4* we = (const float4*)(W_embed + el * CDIM);
    float4* srow = (float4*)(g_s + n * CDIM);
    float4* mrow = (float4*)(g_m + n * CDIM);
#pragma unroll
    for (int q = 0; q < CDIM / 4; q++) {
        srow[q] = we[q];
        mrow[q] = make_float4(0.f, 0.f, 0.f, 0.f);
    }
}

// ---------------------------------------------------------------------------
// edge radial features: bessel * polynomial cutoff
// ---------------------------------------------------------------------------
__global__ void edge_feat_kernel(const float* __restrict__ positions,
                                 const int* __restrict__ edge_index) {
    int e = blockIdx.x * blockDim.x + threadIdx.x;
    if (e >= N_EDGES) return;
    int snd = edge_index[e];
    int rcv = edge_index[N_EDGES + e];

    float dx = positions[rcv * 3 + 0] - positions[snd * 3 + 0];
    float dy = positions[rcv * 3 + 1] - positions[snd * 3 + 1];
    float dz = positions[rcv * 3 + 2] - positions[snd * 3 + 2];
    float r = sqrtf(dx * dx + dy * dy + dz * dz);
    float rs = fmaxf(r, 1e-9f);
    float t = r * 0.2f;

    float4 o0, o1;
    if (t < 1.0f) {
        float t2 = t * t;
        float t5 = t2 * t2 * t;
        float env = 1.0f - 21.0f * t5 + 35.0f * t5 * t - 15.0f * t5 * t2;
        float scale = 0.6324555320336759f * env / rs;
        float x = 0.62831853071795864769f * rs;
        float s1, c1;
        __sincosf(x, &s1, &c1);
        float twoc = 2.0f * c1;
        float sm1 = 0.0f, sn = s1;
        float b[NB];
#pragma unroll
        for (int k = 0; k < NB; k++) {
            b[k] = sn * scale;
            float nxt = twoc * sn - sm1;
            sm1 = sn; sn = nxt;
        }
        o0 = make_float4(b[0], b[1], b[2], b[3]);
        o1 = make_float4(b[4], b[5], b[6], b[7]);
    } else {
        o0 = make_float4(0.f, 0.f, 0.f, 0.f);
        o1 = o0;
    }
    float4* out = (float4*)(g_ef + e * NB);
    out[0] = o0;
    out[1] = o1;
}

// ---------------------------------------------------------------------------
// edge MLP: 8 threads per edge, each owning an 8-column slice.
// ef(8) ->64 ->64 ->64 (l=0 slice of w3); msg = R0*s[snd]; atomicAdd m[rcv].
// 32 edges per block (256 thr), grid-stride over tiles so weights load once.
// ---------------------------------------------------------------------------
#define EPB 32
#define NTILES (N_EDGES / EPB)

__global__ __launch_bounds__(256) void edge_mlp_kernel(
    const float* __restrict__ w1, const float* __restrict__ b1,
    const float* __restrict__ w2, const float* __restrict__ b2,
    const float* __restrict__ w3, const int* __restrict__ edge_index) {
    __shared__ float sw1[NB * CDIM];
    __shared__ float sb1[CDIM];
    __shared__ float sb2[CDIM];
    __shared__ float sw2[CDIM * CDIM];
    __shared__ float sw3[CDIM * CDIM];
    __shared__ float act[EPB * CDIM];

    int tid = threadIdx.x;
    // cooperative weight staging (float4)
    for (int k = tid; k < NB * CDIM / 4; k += 256)
        ((float4*)sw1)[k] = ((const float4*)w1)[k];
    if (tid < CDIM) { sb1[tid] = b1[tid]; sb2[tid] = b2[tid]; }
    for (int k = tid; k < CDIM * CDIM / 4; k += 256)
        ((float4*)sw2)[k] = ((const float4*)w2)[k];
    for (int k = tid; k < CDIM * CDIM / 4; k += 256) {
        int c = k >> 4, jq = k & 15;                 // l=0 slice of (64,256)
        ((float4*)sw3)[c * 16 + jq] = ((const float4*)w3)[c * 64 + jq];
    }
    __syncthreads();

    int e_local = tid >> 3;       // 0..31
    int slice = tid & 7;          // 0..7
    int s8 = slice * 8;
    float* arow = act + e_local * CDIM;

    for (int tile = blockIdx.x; tile < NTILES; tile += gridDim.x) {
        int e = tile * EPB + e_local;

        // edge features (broadcast loads, L1)
        const float4* efv = (const float4*)(g_ef + e * NB);
        float4 e0 = efv[0], e1 = efv[1];
        float ef[NB] = {e0.x, e0.y, e0.z, e0.w, e1.x, e1.y, e1.z, e1.w};

        // ---- layer 1: 8 -> 64 (this thread's 8 outputs) ----
        float a[8];
#pragma unroll
        for (int k = 0; k < 8; k++) a[k] = sb1[s8 + k];
#pragma unroll
        for (int c = 0; c < NB; c++) {
            float x = ef[c];
            const float4* wr = (const float4*)(sw1 + c * CDIM + s8);
            float4 wa = wr[0], wb = wr[1];
            a[0] += x * wa.x; a[1] += x * wa.y; a[2] += x * wa.z; a[3] += x * wa.w;
            a[4] += x * wb.x; a[5] += x * wb.y; a[6] += x * wb.z; a[7] += x * wb.w;
        }
#pragma unroll
        for (int k = 0; k < 8; k++) arow[s8 + k] = silu(a[k]);
        __syncthreads();

        // ---- layer 2: 64 -> 64 (packed f32x2) ----
        unsigned long long acc0 = pack2(sb2[s8 + 0], sb2[s8 + 1]);
        unsigned long long acc1 = pack2(sb2[s8 + 2], sb2[s8 + 3]);
        unsigned long long acc2 = pack2(sb2[s8 + 4], sb2[s8 + 5]);
        unsigned long long acc3 = pack2(sb2[s8 + 6], sb2[s8 + 7]);
#pragma unroll
        for (int c = 0; c < CDIM; c++) {
            float av = arow[c];
            unsigned long long ap = pack2(av, av);
            const ulonglong2* p = (const ulonglong2*)(sw2 + c * CDIM + s8);
            ulonglong2 wa = p[0], wb = p[1];
            acc0 = ffma2(ap, wa.x, acc0);
            acc1 = ffma2(ap, wa.y, acc1);
            acc2 = ffma2(ap, wb.x, acc2);
            acc3 = ffma2(ap, wb.y, acc3);
        }
        float2 b01 = unpack2(acc0), b23 = unpack2(acc1);
        float2 b45 = unpack2(acc2), b67 = unpack2(acc3);
        float bv[8] = {b01.x, b01.y, b23.x, b23.y, b45.x, b45.y, b67.x, b67.y};
        __syncthreads();   // everyone done reading act before overwrite
#pragma unroll
        for (int k = 0; k < 8; k++) arow[s8 + k] = silu(bv[k]);
        __syncthreads();

        // ---- layer 3: 64 -> 64 (no bias/act, packed) ----
        acc0 = 0ull; acc1 = 0ull; acc2 = 0ull; acc3 = 0ull;
#pragma unroll
        for (int c = 0; c < CDIM; c++) {
            float av = arow[c];
            unsigned long long ap = pack2(av, av);
            const ulonglong2* p = (const ulonglong2*)(sw3 + c * CDIM + s8);
            ulonglong2 wa = p[0], wb = p[1];
            acc0 = ffma2(ap, wa.x, acc0);
            acc1 = ffma2(ap, wa.y, acc1);
            acc2 = ffma2(ap, wb.x, acc2);
            acc3 = ffma2(ap, wb.y, acc3);
        }
        float2 r01 = unpack2(acc0), r23 = unpack2(acc1);
        float2 r45 = unpack2(acc2), r67 = unpack2(acc3);
        float out[8] = {r01.x, r01.y, r23.x, r23.y, r45.x, r45.y, r67.x, r67.y};

        // ---- message: msg = R0 * s[snd]; scatter to m[rcv] ----
        int snd = edge_index[e];
        int rcv = edge_index[N_EDGES + e];
        const float4* srow = (const float4*)(g_s + snd * CDIM + s8);
        float4 sv0 = srow[0], sv1 = srow[1];
        float* mrow = g_m + rcv * CDIM + s8;
        atomicAdd(mrow + 0, out[0] * sv0.x);
        atomicAdd(mrow + 1, out[1] * sv0.y);
        atomicAdd(mrow + 2, out[2] * sv0.z);
        atomicAdd(mrow + 3, out[3] * sv0.w);
        atomicAdd(mrow + 4, out[4] * sv1.x);
        atomicAdd(mrow + 5, out[5] * sv1.y);
        atomicAdd(mrow + 6, out[6] * sv1.z);
        atomicAdd(mrow + 7, out[7] * sv1.w);
        __syncthreads();   // act reuse next tile
    }
}

// ---------------------------------------------------------------------------
// node update: 8 threads per node, 32 nodes per block.
// f = (m/8) @ W_lin0; h = f*(w0+w1*f+w2*f^2) + sc*s; energy += h.W_read;
// s = h; m zeroed for next pass.
// ---------------------------------------------------------------------------
#define NPB 32

__global__ __launch_bounds__(256) void node_kernel(
    const float* __restrict__ Wlin0,  // (64,64) l=0 block
    const float* __restrict__ Wprod,  // (3,10,64)
    const float* __restrict__ Wsc,    // (10,64)
    const float* __restrict__ Wread)  // (64,)
{
    __shared__ float swl[CDIM * CDIM];
    __shared__ float m_sm[NPB * CDIM];
    __shared__ float swr[CDIM];

    int tid = threadIdx.x;
    for (int k = tid; k < CDIM * CDIM / 4; k += 256)
        ((float4*)swl)[k] = ((const float4*)Wlin0)[k];
    if (tid < CDIM) swr[tid] = Wread[tid];

    int base = blockIdx.x * NPB * CDIM;
    // cooperative load of m (scaled) + zero g_m
#pragma unroll
    for (int q = 0; q < 2; q++) {
        int idx = (q * 256 + tid);
        float4* gm = (float4*)(g_m + base) + idx;
        float4 v = *gm;
        *gm = make_float4(0.f, 0.f, 0.f, 0.f);
        ((float4*)m_sm)[idx] = make_float4(v.x * 0.125f, v.y * 0.125f,
                                           v.z * 0.125f, v.w * 0.125f);
    }
    __syncthreads();

    int n_local = tid >> 3;
    int slice = tid & 7;
    int s8 = slice * 8;
    int node = blockIdx.x * NPB + n_local;
    const float* mrow = m_sm + n_local * CDIM;

    unsigned long long acc0 = 0ull, acc1 = 0ull, acc2 = 0ull, acc3 = 0ull;
#pragma unroll
    for (int c = 0; c < CDIM; c++) {
        float mv = mrow[c];
        unsigned long long mp = pack2(mv, mv);
        const ulonglong2* p = (const ulonglong2*)(swl + c * CDIM + s8);
        ulonglong2 wa = p[0], wb = p[1];
        acc0 = ffma2(mp, wa.x, acc0);
        acc1 = ffma2(mp, wa.y, acc1);
        acc2 = ffma2(mp, wb.x, acc2);
        acc3 = ffma2(mp, wb.y, acc3);
    }
    float2 f01 = unpack2(acc0), f23 = unpack2(acc1);
    float2 f45 = unpack2(acc2), f67 = unpack2(acc3);
    float f[8] = {f01.x, f01.y, f23.x, f23.y, f45.x, f45.y, f67.x, f67.y};

    int el = g_elem[node];
    const float* w0p = Wprod + (0 * NELEM + el) * CDIM + s8;
    const float* w1p = Wprod + (1 * NELEM + el) * CDIM + s8;
    const float* w2p = Wprod + (2 * NELEM + el) * CDIM + s8;
    const float* scp = Wsc + el * CDIM + s8;
    float* srow = g_s + node * CDIM + s8;

    float energy = 0.0f;
#pragma unroll
    for (int k = 0; k < 8; k++) {
        float fc = f[k];
        float sp = srow[k];
        float h = fc * (w0p[k] + w1p[k] * fc + w2p[k] * fc * fc) + scp[k] * sp;
        srow[k] = h;
        energy += h * swr[s8 + k];
    }
    // reduce across the 8 slice-threads of this node
#pragma unroll
    for (int off = 4; off > 0; off >>= 1)
        energy += __shfl_down_sync(0xffffffffu, energy, off, 8);
    if (slice == 0) g_energy[node] += energy;
}

// ---------------------------------------------------------------------------
// final: segment-sum node energies by graph
// ---------------------------------------------------------------------------
__global__ void final_kernel(const int* __restrict__ batch,
                             float* __restrict__ d_out) {
    __shared__ float bins[NGRAPH];
    if (threadIdx.x < NGRAPH) bins[threadIdx.x] = 0.0f;
    __syncthreads();
    int n = blockIdx.x * blockDim.x + threadIdx.x;
    if (n < N_NODES) atomicAdd(&bins[batch[n]], g_energy[n]);
    __syncthreads();
    if (threadIdx.x < NGRAPH) atomicAdd(d_out + threadIdx.x, bins[threadIdx.x]);
}

// ---------------------------------------------------------------------------
extern "C" void kernel_launch(void* const* d_in, const int* in_sizes, int n_in,
                              void* d_out, int out_size) {
    const float* positions       = (const float*)d_in[0];
    const float* node_attrs      = (const float*)d_in[1];
    const int*   edge_index      = (const int*)d_in[2];
    const int*   batch           = (const int*)d_in[3];
    const float* atomic_energies = (const float*)d_in[4];
    const float* W_embed         = (const float*)d_in[5];
    const float* rw1             = (const float*)d_in[6];
    const float* rb1             = (const float*)d_in[7];
    const float* rw2             = (const float*)d_in[8];
    const float* rb2             = (const float*)d_in[9];
    const float* rw3             = (const float*)d_in[10];
    const float* Wlin            = (const float*)d_in[11];
    const float* Wprod           = (const float*)d_in[12];
    const float* Wsc             = (const float*)d_in[13];
    const float* Wread           = (const float*)d_in[14];
    float* out = (float*)d_out;

    init_kernel<<<N_NODES / 128, 128>>>(node_attrs, atomic_energies, W_embed, out);
    edge_feat_kernel<<<N_EDGES / 256, 256>>>(positions, edge_index);
    for (int i = 0; i < 2; i++) {
        edge_mlp_kernel<<<512, 256>>>(
            rw1 + i * NB * CDIM, rb1 + i * CDIM,
            rw2 + i * CDIM * CDIM, rb2 + i * CDIM,
            rw3 + i * CDIM * 4 * CDIM, edge_index);
        node_kernel<<<N_NODES / NPB, 256>>>(
            Wlin + i * 4 * CDIM * CDIM,
            Wprod + i * 3 * NELEM * CDIM,
            Wsc + i * NELEM * CDIM,
            Wread + i * CDIM);
    }
    final_kernel<<<N_NODES / 256, 256>>>(batch, out);
}

// round 5
// speedup vs baseline: 1.9926x; 1.9926x over previous
#include <cuda_runtime.h>
#include <math.h>

#define N_NODES 8192
#define N_EDGES 65536
#define CDIM 64
#define NB 8
#define NELEM 10
#define NGRAPH 8

// Scratch (device globals; no allocation allowed)
__device__ float g_s[N_NODES * CDIM];
__device__ float g_m[N_NODES * CDIM];
__device__ float g_energy[N_NODES];
__device__ float g_ef[N_EDGES * NB];
__device__ int   g_elem[N_NODES];

// ---------------- packed f32x2 helpers (Blackwell FFMA2) -------------------
__device__ __forceinline__ unsigned long long pack2(float x, float y) {
    unsigned long long r;
    asm("mov.b64 %0, {%1, %2};" : "=l"(r) : "f"(x), "f"(y));
    return r;
}
__device__ __forceinline__ unsigned long long ffma2(unsigned long long a,
                                                    unsigned long long b,
                                                    unsigned long long c) {
    unsigned long long d;
    asm("fma.rn.f32x2 %0, %1, %2, %3;" : "=l"(d) : "l"(a), "l"(b), "l"(c));
    return d;
}
__device__ __forceinline__ float2 unpack2(unsigned long long v) {
    float x, y;
    asm("mov.b64 {%0, %1}, %2;" : "=f"(x), "=f"(y) : "l"(v));
    return make_float2(x, y);
}
__device__ __forceinline__ float silu(float x) {
    return __fdividef(x, 1.0f + __expf(-x));
}

// ---------------------------------------------------------------------------
__global__ void init_kernel(const float* __restrict__ node_attrs,
                            const float* __restrict__ atomic_energies,
                            const float* __restrict__ W_embed,
                            float* __restrict__ d_out) {
    int n = blockIdx.x * blockDim.x + threadIdx.x;
    if (n >= N_NODES) return;
    if (n < NGRAPH) d_out[n] = 0.0f;

    const float* row = node_attrs + n * NELEM;
    int el = 0;
#pragma unroll
    for (int k = 0; k < NELEM; k++)
        if (row[k] > 0.5f) el = k;
    g_elem[n] = el;
    g_energy[n] = atomic_energies[el];

    const float4* we = (const float4*)(W_embed + el * CDIM);
    float4* srow = (float4*)(g_s + n * CDIM);
    float4* mrow = (float4*)(g_m + n * CDIM);
#pragma unroll
    for (int q = 0; q < CDIM / 4; q++) {
        srow[q] = we[q];
        mrow[q] = make_float4(0.f, 0.f, 0.f, 0.f);
    }
}

// ---------------------------------------------------------------------------
__global__ void edge_feat_kernel(const float* __restrict__ positions,
                                 const int* __restrict__ edge_index) {
    int e = blockIdx.x * blockDim.x + threadIdx.x;
    if (e >= N_EDGES) return;
    int snd = edge_index[e];
    int rcv = edge_index[N_EDGES + e];

    float dx = positions[rcv * 3 + 0] - positions[snd * 3 + 0];
    float dy = positions[rcv * 3 + 1] - positions[snd * 3 + 1];
    float dz = positions[rcv * 3 + 2] - positions[snd * 3 + 2];
    float r = sqrtf(dx * dx + dy * dy + dz * dz);
    float rs = fmaxf(r, 1e-9f);
    float t = r * 0.2f;

    float4 o0, o1;
    if (t < 1.0f) {
        float t2 = t * t;
        float t5 = t2 * t2 * t;
        float env = 1.0f - 21.0f * t5 + 35.0f * t5 * t - 15.0f * t5 * t2;
        float scale = 0.6324555320336759f * env / rs;
        float x = 0.62831853071795864769f * rs;
        float s1, c1;
        __sincosf(x, &s1, &c1);
        float twoc = 2.0f * c1;
        float sm1 = 0.0f, sn = s1;
        float b[NB];
#pragma unroll
        for (int k = 0; k < NB; k++) {
            b[k] = sn * scale;
            float nxt = twoc * sn - sm1;
            sm1 = sn; sn = nxt;
        }
        o0 = make_float4(b[0], b[1], b[2], b[3]);
        o1 = make_float4(b[4], b[5], b[6], b[7]);
    } else {
        o0 = make_float4(0.f, 0.f, 0.f, 0.f);
        o1 = o0;
    }
    float4* out = (float4*)(g_ef + e * NB);
    out[0] = o0;
    out[1] = o1;
}

// ---------------------------------------------------------------------------
// edge MLP: block = 256 threads = 8 warps. warp w owns output slice
// [w*8, w*8+8); thread (warp, lane g) processes 4 edges (block: 128 edges).
// Weight smem loads are warp-uniform (broadcast) and amortized over 4 edges
// (16 FFMA2 per 32B of LDS). Activations staged transposed act[c][edge].
// ---------------------------------------------------------------------------
#define EPB 128

__global__ __launch_bounds__(256) void edge_mlp_kernel(
    const float* __restrict__ w1, const float* __restrict__ b1,
    const float* __restrict__ w2, const float* __restrict__ b2,
    const float* __restrict__ w3, const int* __restrict__ edge_index) {
    extern __shared__ float smp[];
    float* sw2 = smp;              // 4096
    float* sw3 = smp + 4096;       // 4096
    float* act = smp + 8192;       // 8192 (transposed: [c][edge])
    float* sw1 = smp + 16384;      // 512
    float* sb1 = smp + 16896;      // 64
    float* sb2 = smp + 16960;      // 64

    int tid = threadIdx.x;
    for (int k = tid; k < 1024; k += 256)
        ((float4*)sw2)[k] = ((const float4*)w2)[k];
    for (int k = tid; k < 1024; k += 256) {
        int c = k >> 4, jq = k & 15;          // l=0 slice of (64,256)
        ((float4*)sw3)[k] = ((const float4*)w3)[c * 64 + jq];
    }
    for (int k = tid; k < 128; k += 256)
        ((float4*)sw1)[k] = ((const float4*)w1)[k];
    if (tid < 64) { sb1[tid] = b1[tid]; sb2[tid] = b2[tid]; }
    __syncthreads();

    int slice = tid >> 5;          // warp id = output slice
    int g = tid & 31;              // lane = edge group
    int s8 = slice * 8;
    int ebase = blockIdx.x * EPB + g * 4;

    // ---- load edge features for 4 edges ----
    float ef[4][8];
#pragma unroll
    for (int e = 0; e < 4; e++) {
        const float4* v = (const float4*)(g_ef + (ebase + e) * NB);
        float4 v0 = v[0], v1 = v[1];
        ef[e][0] = v0.x; ef[e][1] = v0.y; ef[e][2] = v0.z; ef[e][3] = v0.w;
        ef[e][4] = v1.x; ef[e][5] = v1.y; ef[e][6] = v1.z; ef[e][7] = v1.w;
    }

    // ---- layer 1: 8 -> 64 ----
    float a[4][8];
#pragma unroll
    for (int e = 0; e < 4; e++)
#pragma unroll
        for (int k = 0; k < 8; k++) a[e][k] = sb1[s8 + k];
#pragma unroll
    for (int c = 0; c < NB; c++) {
        float4 wa = *(const float4*)(sw1 + c * CDIM + s8);
        float4 wb = *(const float4*)(sw1 + c * CDIM + s8 + 4);
#pragma unroll
        for (int e = 0; e < 4; e++) {
            float x = ef[e][c];
            a[e][0] += x * wa.x; a[e][1] += x * wa.y;
            a[e][2] += x * wa.z; a[e][3] += x * wa.w;
            a[e][4] += x * wb.x; a[e][5] += x * wb.y;
            a[e][6] += x * wb.z; a[e][7] += x * wb.w;
        }
    }
#pragma unroll
    for (int k = 0; k < 8; k++) {
        float4 t = make_float4(silu(a[0][k]), silu(a[1][k]),
                               silu(a[2][k]), silu(a[3][k]));
        *(float4*)(act + (s8 + k) * EPB + g * 4) = t;
    }
    __syncthreads();

    // ---- layer 2: 64 -> 64 ----
    unsigned long long acc[4][4];
#pragma unroll
    for (int i = 0; i < 4; i++) {
        unsigned long long bi = pack2(sb2[s8 + 2 * i], sb2[s8 + 2 * i + 1]);
#pragma unroll
        for (int e = 0; e < 4; e++) acc[e][i] = bi;
    }
#pragma unroll 16
    for (int c = 0; c < CDIM; c++) {
        float4 av = *(const float4*)(act + c * EPB + g * 4);
        ulonglong2 wA = *(const ulonglong2*)(sw2 + c * CDIM + s8);
        ulonglong2 wB = *(const ulonglong2*)(sw2 + c * CDIM + s8 + 4);
        unsigned long long a0 = pack2(av.x, av.x);
        unsigned long long a1 = pack2(av.y, av.y);
        unsigned long long a2 = pack2(av.z, av.z);
        unsigned long long a3 = pack2(av.w, av.w);
        acc[0][0] = ffma2(a0, wA.x, acc[0][0]);
        acc[0][1] = ffma2(a0, wA.y, acc[0][1]);
        acc[0][2] = ffma2(a0, wB.x, acc[0][2]);
        acc[0][3] = ffma2(a0, wB.y, acc[0][3]);
        acc[1][0] = ffma2(a1, wA.x, acc[1][0]);
        acc[1][1] = ffma2(a1, wA.y, acc[1][1]);
        acc[1][2] = ffma2(a1, wB.x, acc[1][2]);
        acc[1][3] = ffma2(a1, wB.y, acc[1][3]);
        acc[2][0] = ffma2(a2, wA.x, acc[2][0]);
        acc[2][1] = ffma2(a2, wA.y, acc[2][1]);
        acc[2][2] = ffma2(a2, wB.x, acc[2][2]);
        acc[2][3] = ffma2(a2, wB.y, acc[2][3]);
        acc[3][0] = ffma2(a3, wA.x, acc[3][0]);
        acc[3][1] = ffma2(a3, wA.y, acc[3][1]);
        acc[3][2] = ffma2(a3, wB.x, acc[3][2]);
        acc[3][3] = ffma2(a3, wB.y, acc[3][3]);
    }
    __syncthreads();           // all reads of act done
#pragma unroll
    for (int i = 0; i < 4; i++) {
        float2 p0 = unpack2(acc[0][i]);
        float2 p1 = unpack2(acc[1][i]);
        float2 p2 = unpack2(acc[2][i]);
        float2 p3 = unpack2(acc[3][i]);
        float4 lo = make_float4(silu(p0.x), silu(p1.x), silu(p2.x), silu(p3.x));
        float4 hi = make_float4(silu(p0.y), silu(p1.y), silu(p2.y), silu(p3.y));
        *(float4*)(act + (s8 + 2 * i) * EPB + g * 4) = lo;
        *(float4*)(act + (s8 + 2 * i + 1) * EPB + g * 4) = hi;
    }
    __syncthreads();

    // ---- layer 3: 64 -> 64 (no bias/act) ----
#pragma unroll
    for (int e = 0; e < 4; e++)
#pragma unroll
        for (int i = 0; i < 4; i++) acc[e][i] = 0ull;
#pragma unroll 16
    for (int c = 0; c < CDIM; c++) {
        float4 av = *(const float4*)(act + c * EPB + g * 4);
        ulonglong2 wA = *(const ulonglong2*)(sw3 + c * CDIM + s8);
        ulonglong2 wB = *(const ulonglong2*)(sw3 + c * CDIM + s8 + 4);
        unsigned long long a0 = pack2(av.x, av.x);
        unsigned long long a1 = pack2(av.y, av.y);
        unsigned long long a2 = pack2(av.z, av.z);
        unsigned long long a3 = pack2(av.w, av.w);
        acc[0][0] = ffma2(a0, wA.x, acc[0][0]);
        acc[0][1] = ffma2(a0, wA.y, acc[0][1]);
        acc[0][2] = ffma2(a0, wB.x, acc[0][2]);
        acc[0][3] = ffma2(a0, wB.y, acc[0][3]);
        acc[1][0] = ffma2(a1, wA.x, acc[1][0]);
        acc[1][1] = ffma2(a1, wA.y, acc[1][1]);
        acc[1][2] = ffma2(a1, wB.x, acc[1][2]);
        acc[1][3] = ffma2(a1, wB.y, acc[1][3]);
        acc[2][0] = ffma2(a2, wA.x, acc[2][0]);
        acc[2][1] = ffma2(a2, wA.y, acc[2][1]);
        acc[2][2] = ffma2(a2, wB.x, acc[2][2]);
        acc[2][3] = ffma2(a2, wB.y, acc[2][3]);
        acc[3][0] = ffma2(a3, wA.x, acc[3][0]);
        acc[3][1] = ffma2(a3, wA.y, acc[3][1]);
        acc[3][2] = ffma2(a3, wB.x, acc[3][2]);
        acc[3][3] = ffma2(a3, wB.y, acc[3][3]);
    }

    // ---- message: msg = R0 * s[snd]; scatter to m[rcv] ----
    int4 snd4 = *(const int4*)(edge_index + ebase);
    int4 rcv4 = *(const int4*)(edge_index + N_EDGES + ebase);
    const int* snds = &snd4.x;
    const int* rcvs = &rcv4.x;
#pragma unroll
    for (int e = 0; e < 4; e++) {
        float o[8];
#pragma unroll
        for (int i = 0; i < 4; i++) {
            float2 p = unpack2(acc[e][i]);
            o[2 * i] = p.x; o[2 * i + 1] = p.y;
        }
        int snd = snds[e], rcv = rcvs[e];
        const float4* srow = (const float4*)(g_s + snd * CDIM + s8);
        float4 sv0 = srow[0], sv1 = srow[1];
        float* mrow = g_m + rcv * CDIM + s8;
        atomicAdd(mrow + 0, o[0] * sv0.x);
        atomicAdd(mrow + 1, o[1] * sv0.y);
        atomicAdd(mrow + 2, o[2] * sv0.z);
        atomicAdd(mrow + 3, o[3] * sv0.w);
        atomicAdd(mrow + 4, o[4] * sv1.x);
        atomicAdd(mrow + 5, o[5] * sv1.y);
        atomicAdd(mrow + 6, o[6] * sv1.z);
        atomicAdd(mrow + 7, o[7] * sv1.w);
    }
}

// ---------------------------------------------------------------------------
// node update: 64 nodes/block, thread (slice, g) handles 2 nodes x 8 cols.
// ---------------------------------------------------------------------------
#define NPB 64

__global__ __launch_bounds__(256) void node_kernel(
    const float* __restrict__ Wlin0,
    const float* __restrict__ Wprod,
    const float* __restrict__ Wsc,
    const float* __restrict__ Wread) {
    __shared__ float swl[CDIM * CDIM];
    __shared__ float m_t[CDIM * NPB];     // transposed [c][node]
    __shared__ float swr[CDIM];

    int tid = threadIdx.x;
    for (int k = tid; k < 1024; k += 256)
        ((float4*)swl)[k] = ((const float4*)Wlin0)[k];
    if (tid < CDIM) swr[tid] = Wread[tid];

    // cooperative transpose-load of m (scaled), zero g_m for next pass
    float4* gm = (float4*)(g_m + blockIdx.x * NPB * CDIM);
#pragma unroll
    for (int q = 0; q < 4; q++) {
        int idx = q * 256 + tid;            // 0..1023
        int node_local = idx & 63;
        int c4 = idx >> 6;
        float4 v = gm[node_local * 16 + c4];
        gm[node_local * 16 + c4] = make_float4(0.f, 0.f, 0.f, 0.f);
        m_t[(c4 * 4 + 0) * NPB + node_local] = v.x * 0.125f;
        m_t[(c4 * 4 + 1) * NPB + node_local] = v.y * 0.125f;
        m_t[(c4 * 4 + 2) * NPB + node_local] = v.z * 0.125f;
        m_t[(c4 * 4 + 3) * NPB + node_local] = v.w * 0.125f;
    }
    __syncthreads();

    int slice = tid >> 5;
    int g = tid & 31;
    int s8 = slice * 8;

    unsigned long long acc[2][4];
#pragma unroll
    for (int e = 0; e < 2; e++)
#pragma unroll
        for (int i = 0; i < 4; i++) acc[e][i] = 0ull;

#pragma unroll 16
    for (int c = 0; c < CDIM; c++) {
        float2 av = *(const float2*)(m_t + c * NPB + g * 2);
        ulonglong2 wA = *(const ulonglong2*)(swl + c * CDIM + s8);
        ulonglong2 wB = *(const ulonglong2*)(swl + c * CDIM + s8 + 4);
        unsigned long long a0 = pack2(av.x, av.x);
        unsigned long long a1 = pack2(av.y, av.y);
        acc[0][0] = ffma2(a0, wA.x, acc[0][0]);
        acc[0][1] = ffma2(a0, wA.y, acc[0][1]);
        acc[0][2] = ffma2(a0, wB.x, acc[0][2]);
        acc[0][3] = ffma2(a0, wB.y, acc[0][3]);
        acc[1][0] = ffma2(a1, wA.x, acc[1][0]);
        acc[1][1] = ffma2(a1, wA.y, acc[1][1]);
        acc[1][2] = ffma2(a1, wB.x, acc[1][2]);
        acc[1][3] = ffma2(a1, wB.y, acc[1][3]);
    }

#pragma unroll
    for (int e = 0; e < 2; e++) {
        int node = blockIdx.x * NPB + g * 2 + e;
        float f[8];
#pragma unroll
        for (int i = 0; i < 4; i++) {
            float2 p = unpack2(acc[e][i]);
            f[2 * i] = p.x; f[2 * i + 1] = p.y;
        }
        int el = g_elem[node];
        const float* w0p = Wprod + (0 * NELEM + el) * CDIM + s8;
        const float* w1p = Wprod + (1 * NELEM + el) * CDIM + s8;
        const float* w2p = Wprod + (2 * NELEM + el) * CDIM + s8;
        const float* scp = Wsc + el * CDIM + s8;
        float* srow = g_s + node * CDIM + s8;

        float energy = 0.0f;
#pragma unroll
        for (int k = 0; k < 8; k++) {
            float fc = f[k];
            float sp = srow[k];
            float h = fc * (w0p[k] + w1p[k] * fc + w2p[k] * fc * fc) + scp[k] * sp;
            srow[k] = h;
            energy += h * swr[s8 + k];
        }
        atomicAdd(&g_energy[node], energy);
    }
}

// ---------------------------------------------------------------------------
__global__ void final_kernel(const int* __restrict__ batch,
                             float* __restrict__ d_out) {
    __shared__ float bins[NGRAPH];
    if (threadIdx.x < NGRAPH) bins[threadIdx.x] = 0.0f;
    __syncthreads();
    int n = blockIdx.x * blockDim.x + threadIdx.x;
    if (n < N_NODES) atomicAdd(&bins[batch[n]], g_energy[n]);
    __syncthreads();
    if (threadIdx.x < NGRAPH) atomicAdd(d_out + threadIdx.x, bins[threadIdx.x]);
}

// ---------------------------------------------------------------------------
extern "C" void kernel_launch(void* const* d_in, const int* in_sizes, int n_in,
                              void* d_out, int out_size) {
    const float* positions       = (const float*)d_in[0];
    const float* node_attrs      = (const float*)d_in[1];
    const int*   edge_index      = (const int*)d_in[2];
    const int*   batch           = (const int*)d_in[3];
    const float* atomic_energies = (const float*)d_in[4];
    const float* W_embed         = (const float*)d_in[5];
    const float* rw1             = (const float*)d_in[6];
    const float* rb1             = (const float*)d_in[7];
    const float* rw2             = (const float*)d_in[8];
    const float* rb2             = (const float*)d_in[9];
    const float* rw3             = (const float*)d_in[10];
    const float* Wlin            = (const float*)d_in[11];
    const float* Wprod           = (const float*)d_in[12];
    const float* Wsc             = (const float*)d_in[13];
    const float* Wread           = (const float*)d_in[14];
    float* out = (float*)d_out;

    const int EDGE_SMEM = 17024 * 4;   // 68096 B dynamic
    cudaFuncSetAttribute(edge_mlp_kernel,
                         cudaFuncAttributeMaxDynamicSharedMemorySize, EDGE_SMEM);

    init_kernel<<<N_NODES / 128, 128>>>(node_attrs, atomic_energies, W_embed, out);
    edge_feat_kernel<<<N_EDGES / 256, 256>>>(positions, edge_index);
    for (int i = 0; i < 2; i++) {
        edge_mlp_kernel<<<N_EDGES / EPB, 256, EDGE_SMEM>>>(
            rw1 + i * NB * CDIM, rb1 + i * CDIM,
            rw2 + i * CDIM * CDIM, rb2 + i * CDIM,
            rw3 + i * CDIM * 4 * CDIM, edge_index);
        node_kernel<<<N_NODES / NPB, 256>>>(
            Wlin + i * 4 * CDIM * CDIM,
            Wprod + i * 3 * NELEM * CDIM,
            Wsc + i * NELEM * CDIM,
            Wread + i * CDIM);
    }
    final_kernel<<<N_NODES / 256, 256>>>(batch, out);
}

// round 6
// speedup vs baseline: 2.6906x; 1.3503x over previous
#include <cuda_runtime.h>
#include <math.h>

#define N_NODES 8192
#define N_EDGES 65536
#define CDIM 64
#define NB 8
#define NELEM 10
#define NGRAPH 8

// Scratch (device globals; no allocation allowed)
__device__ float g_s[N_NODES * CDIM];
__device__ float g_m[N_NODES * CDIM];
__device__ float g_energy[N_NODES];
__device__ float g_ef[N_EDGES * NB];
__device__ int   g_elem[N_NODES];

// ---------------- packed f32x2 helpers (Blackwell FFMA2) -------------------
__device__ __forceinline__ unsigned long long pack2(float x, float y) {
    unsigned long long r;
    asm("mov.b64 %0, {%1, %2};" : "=l"(r) : "f"(x), "f"(y));
    return r;
}
__device__ __forceinline__ unsigned long long ffma2(unsigned long long a,
                                                    unsigned long long b,
                                                    unsigned long long c) {
    unsigned long long d;
    asm("fma.rn.f32x2 %0, %1, %2, %3;" : "=l"(d) : "l"(a), "l"(b), "l"(c));
    return d;
}
__device__ __forceinline__ float2 unpack2(unsigned long long v) {
    float x, y;
    asm("mov.b64 {%0, %1}, %2;" : "=f"(x), "=f"(y) : "l"(v));
    return make_float2(x, y);
}
__device__ __forceinline__ float silu(float x) {
    return __fdividef(x, 1.0f + __expf(-x));
}

// ---------------------------------------------------------------------------
__global__ void init_kernel(const float* __restrict__ node_attrs,
                            const float* __restrict__ atomic_energies,
                            const float* __restrict__ W_embed,
                            float* __restrict__ d_out) {
    int n = blockIdx.x * blockDim.x + threadIdx.x;
    if (n >= N_NODES) return;
    if (n < NGRAPH) d_out[n] = 0.0f;

    const float* row = node_attrs + n * NELEM;
    int el = 0;
#pragma unroll
    for (int k = 0; k < NELEM; k++)
        if (row[k] > 0.5f) el = k;
    g_elem[n] = el;
    g_energy[n] = atomic_energies[el];

    const float4* we = (const float4*)(W_embed + el * CDIM);
    float4* srow = (float4*)(g_s + n * CDIM);
    float4* mrow = (float4*)(g_m + n * CDIM);
#pragma unroll
    for (int q = 0; q < CDIM / 4; q++) {
        srow[q] = we[q];
        mrow[q] = make_float4(0.f, 0.f, 0.f, 0.f);
    }
}

// ---------------------------------------------------------------------------
// edge features for one edge (bessel * poly cutoff); sh[:,0]==1
// ---------------------------------------------------------------------------
__device__ __forceinline__ void compute_ef(const float* __restrict__ positions,
                                           int snd, int rcv, float* ef) {
    float dx = positions[rcv * 3 + 0] - positions[snd * 3 + 0];
    float dy = positions[rcv * 3 + 1] - positions[snd * 3 + 1];
    float dz = positions[rcv * 3 + 2] - positions[snd * 3 + 2];
    float r = sqrtf(dx * dx + dy * dy + dz * dz);
    float rs = fmaxf(r, 1e-9f);
    float t = r * 0.2f;
    if (t < 1.0f) {
        float t2 = t * t;
        float t5 = t2 * t2 * t;
        float env = 1.0f - 21.0f * t5 + 35.0f * t5 * t - 15.0f * t5 * t2;
        float scale = 0.6324555320336759f * env / rs;
        float x = 0.62831853071795864769f * rs;
        float s1, c1;
        __sincosf(x, &s1, &c1);
        float twoc = 2.0f * c1;
        float sm1 = 0.0f, sn = s1;
#pragma unroll
        for (int k = 0; k < NB; k++) {
            ef[k] = sn * scale;
            float nxt = twoc * sn - sm1;
            sm1 = sn; sn = nxt;
        }
    } else {
#pragma unroll
        for (int k = 0; k < NB; k++) ef[k] = 0.0f;
    }
}

// ---------------------------------------------------------------------------
// edge MLP: block = 256 threads = 8 warps. warp w owns output slice
// [w*8, w*8+8); thread (warp, lane g) processes 4 edges (block: 128 edges).
// first!=0: compute edge features inline and persist them to g_ef.
// ---------------------------------------------------------------------------
#define EPB 128

__global__ __launch_bounds__(256) void edge_mlp_kernel(
    const float* __restrict__ w1, const float* __restrict__ b1,
    const float* __restrict__ w2, const float* __restrict__ b2,
    const float* __restrict__ w3, const int* __restrict__ edge_index,
    const float* __restrict__ positions, int first) {
    extern __shared__ float smp[];
    float* sw2 = smp;              // 4096
    float* sw3 = smp + 4096;       // 4096
    float* act = smp + 8192;       // 8192 (transposed: [c][edge])
    float* sw1 = smp + 16384;      // 512
    float* sb1 = smp + 16896;      // 64
    float* sb2 = smp + 16960;      // 64

    int tid = threadIdx.x;
    for (int k = tid; k < 1024; k += 256)
        ((float4*)sw2)[k] = ((const float4*)w2)[k];
    for (int k = tid; k < 1024; k += 256) {
        int c = k >> 4, jq = k & 15;          // l=0 slice of (64,256)
        ((float4*)sw3)[k] = ((const float4*)w3)[c * 64 + jq];
    }
    for (int k = tid; k < 128; k += 256)
        ((float4*)sw1)[k] = ((const float4*)w1)[k];
    if (tid < 64) { sb1[tid] = b1[tid]; sb2[tid] = b2[tid]; }

    int slice = tid >> 5;          // warp id = output slice
    int g = tid & 31;              // lane = edge group
    int s8 = slice * 8;
    int ebase = blockIdx.x * EPB + g * 4;

    int4 snd4 = *(const int4*)(edge_index + ebase);
    int4 rcv4 = *(const int4*)(edge_index + N_EDGES + ebase);
    const int* snds = &snd4.x;
    const int* rcvs = &rcv4.x;

    // ---- edge features for 4 edges ----
    float ef[4][8];
    if (first) {
#pragma unroll
        for (int e = 0; e < 4; e++) {
            compute_ef(positions, snds[e], rcvs[e], ef[e]);
            float4* out = (float4*)(g_ef + (ebase + e) * NB);
            out[0] = make_float4(ef[e][0], ef[e][1], ef[e][2], ef[e][3]);
            out[1] = make_float4(ef[e][4], ef[e][5], ef[e][6], ef[e][7]);
        }
    } else {
#pragma unroll
        for (int e = 0; e < 4; e++) {
            const float4* v = (const float4*)(g_ef + (ebase + e) * NB);
            float4 v0 = v[0], v1 = v[1];
            ef[e][0] = v0.x; ef[e][1] = v0.y; ef[e][2] = v0.z; ef[e][3] = v0.w;
            ef[e][4] = v1.x; ef[e][5] = v1.y; ef[e][6] = v1.z; ef[e][7] = v1.w;
        }
    }
    __syncthreads();

    // ---- layer 1: 8 -> 64 ----
    float a[4][8];
#pragma unroll
    for (int e = 0; e < 4; e++)
#pragma unroll
        for (int k = 0; k < 8; k++) a[e][k] = sb1[s8 + k];
#pragma unroll
    for (int c = 0; c < NB; c++) {
        float4 wa = *(const float4*)(sw1 + c * CDIM + s8);
        float4 wb = *(const float4*)(sw1 + c * CDIM + s8 + 4);
#pragma unroll
        for (int e = 0; e < 4; e++) {
            float x = ef[e][c];
            a[e][0] += x * wa.x; a[e][1] += x * wa.y;
            a[e][2] += x * wa.z; a[e][3] += x * wa.w;
            a[e][4] += x * wb.x; a[e][5] += x * wb.y;
            a[e][6] += x * wb.z; a[e][7] += x * wb.w;
        }
    }
#pragma unroll
    for (int k = 0; k < 8; k++) {
        float4 t = make_float4(silu(a[0][k]), silu(a[1][k]),
                               silu(a[2][k]), silu(a[3][k]));
        *(float4*)(act + (s8 + k) * EPB + g * 4) = t;
    }
    __syncthreads();

    // ---- layer 2: 64 -> 64 ----
    unsigned long long acc[4][4];
#pragma unroll
    for (int i = 0; i < 4; i++) {
        unsigned long long bi = pack2(sb2[s8 + 2 * i], sb2[s8 + 2 * i + 1]);
#pragma unroll
        for (int e = 0; e < 4; e++) acc[e][i] = bi;
    }
#pragma unroll 16
    for (int c = 0; c < CDIM; c++) {
        float4 av = *(const float4*)(act + c * EPB + g * 4);
        ulonglong2 wA = *(const ulonglong2*)(sw2 + c * CDIM + s8);
        ulonglong2 wB = *(const ulonglong2*)(sw2 + c * CDIM + s8 + 4);
        unsigned long long a0 = pack2(av.x, av.x);
        unsigned long long a1 = pack2(av.y, av.y);
        unsigned long long a2 = pack2(av.z, av.z);
        unsigned long long a3 = pack2(av.w, av.w);
        acc[0][0] = ffma2(a0, wA.x, acc[0][0]);
        acc[0][1] = ffma2(a0, wA.y, acc[0][1]);
        acc[0][2] = ffma2(a0, wB.x, acc[0][2]);
        acc[0][3] = ffma2(a0, wB.y, acc[0][3]);
        acc[1][0] = ffma2(a1, wA.x, acc[1][0]);
        acc[1][1] = ffma2(a1, wA.y, acc[1][1]);
        acc[1][2] = ffma2(a1, wB.x, acc[1][2]);
        acc[1][3] = ffma2(a1, wB.y, acc[1][3]);
        acc[2][0] = ffma2(a2, wA.x, acc[2][0]);
        acc[2][1] = ffma2(a2, wA.y, acc[2][1]);
        acc[2][2] = ffma2(a2, wB.x, acc[2][2]);
        acc[2][3] = ffma2(a2, wB.y, acc[2][3]);
        acc[3][0] = ffma2(a3, wA.x, acc[3][0]);
        acc[3][1] = ffma2(a3, wA.y, acc[3][1]);
        acc[3][2] = ffma2(a3, wB.x, acc[3][2]);
        acc[3][3] = ffma2(a3, wB.y, acc[3][3]);
    }
    __syncthreads();           // all reads of act done
#pragma unroll
    for (int i = 0; i < 4; i++) {
        float2 p0 = unpack2(acc[0][i]);
        float2 p1 = unpack2(acc[1][i]);
        float2 p2 = unpack2(acc[2][i]);
        float2 p3 = unpack2(acc[3][i]);
        float4 lo = make_float4(silu(p0.x), silu(p1.x), silu(p2.x), silu(p3.x));
        float4 hi = make_float4(silu(p0.y), silu(p1.y), silu(p2.y), silu(p3.y));
        *(float4*)(act + (s8 + 2 * i) * EPB + g * 4) = lo;
        *(float4*)(act + (s8 + 2 * i + 1) * EPB + g * 4) = hi;
    }
    __syncthreads();

    // ---- layer 3: 64 -> 64 (no bias/act) ----
#pragma unroll
    for (int e = 0; e < 4; e++)
#pragma unroll
        for (int i = 0; i < 4; i++) acc[e][i] = 0ull;
#pragma unroll 16
    for (int c = 0; c < CDIM; c++) {
        float4 av = *(const float4*)(act + c * EPB + g * 4);
        ulonglong2 wA = *(const ulonglong2*)(sw3 + c * CDIM + s8);
        ulonglong2 wB = *(const ulonglong2*)(sw3 + c * CDIM + s8 + 4);
        unsigned long long a0 = pack2(av.x, av.x);
        unsigned long long a1 = pack2(av.y, av.y);
        unsigned long long a2 = pack2(av.z, av.z);
        unsigned long long a3 = pack2(av.w, av.w);
        acc[0][0] = ffma2(a0, wA.x, acc[0][0]);
        acc[0][1] = ffma2(a0, wA.y, acc[0][1]);
        acc[0][2] = ffma2(a0, wB.x, acc[0][2]);
        acc[0][3] = ffma2(a0, wB.y, acc[0][3]);
        acc[1][0] = ffma2(a1, wA.x, acc[1][0]);
        acc[1][1] = ffma2(a1, wA.y, acc[1][1]);
        acc[1][2] = ffma2(a1, wB.x, acc[1][2]);
        acc[1][3] = ffma2(a1, wB.y, acc[1][3]);
        acc[2][0] = ffma2(a2, wA.x, acc[2][0]);
        acc[2][1] = ffma2(a2, wA.y, acc[2][1]);
        acc[2][2] = ffma2(a2, wB.x, acc[2][2]);
        acc[2][3] = ffma2(a2, wB.y, acc[2][3]);
        acc[3][0] = ffma2(a3, wA.x, acc[3][0]);
        acc[3][1] = ffma2(a3, wA.y, acc[3][1]);
        acc[3][2] = ffma2(a3, wB.x, acc[3][2]);
        acc[3][3] = ffma2(a3, wB.y, acc[3][3]);
    }

    // ---- message: msg = R0 * s[snd]; scatter to m[rcv] ----
#pragma unroll
    for (int e = 0; e < 4; e++) {
        float o[8];
#pragma unroll
        for (int i = 0; i < 4; i++) {
            float2 p = unpack2(acc[e][i]);
            o[2 * i] = p.x; o[2 * i + 1] = p.y;
        }
        int snd = snds[e], rcv = rcvs[e];
        const float4* srow = (const float4*)(g_s + snd * CDIM + s8);
        float4 sv0 = srow[0], sv1 = srow[1];
        float* mrow = g_m + rcv * CDIM + s8;
        atomicAdd(mrow + 0, o[0] * sv0.x);
        atomicAdd(mrow + 1, o[1] * sv0.y);
        atomicAdd(mrow + 2, o[2] * sv0.z);
        atomicAdd(mrow + 3, o[3] * sv0.w);
        atomicAdd(mrow + 4, o[4] * sv1.x);
        atomicAdd(mrow + 5, o[5] * sv1.y);
        atomicAdd(mrow + 6, o[6] * sv1.z);
        atomicAdd(mrow + 7, o[7] * sv1.w);
    }
}

// ---------------------------------------------------------------------------
// node update v3: warp-per-node. Block = 256 thr = 8 warps, 32 nodes/block
// (4 nodes per warp, processed in 2 weight-sharing pairs).
// m staged into smem COALESCED/untransposed; in the c-loop all lanes read
// m_sm[node][c] as a broadcast; weight pair via conflict-free LDS.64.
// last!=0: fold the per-graph segment sum (smem bins + global atomics).
// ---------------------------------------------------------------------------
#define NPB 32

__global__ __launch_bounds__(256) void node_kernel(
    const float* __restrict__ Wlin0,
    const float* __restrict__ Wprod,
    const float* __restrict__ Wsc,
    const float* __restrict__ Wread,
    const int* __restrict__ batch,
    float* __restrict__ d_out, int last) {
    __shared__ float swl[CDIM * CDIM];
    __shared__ float m_sm[NPB * CDIM];
    __shared__ float bins[NGRAPH];

    int tid = threadIdx.x;
    for (int k = tid; k < 1024; k += 256)
        ((float4*)swl)[k] = ((const float4*)Wlin0)[k];

    // coalesced m stage (scaled by 1/8) + zero g_m for next accumulate pass
    float4* gm = (float4*)(g_m + blockIdx.x * NPB * CDIM);
#pragma unroll
    for (int q = 0; q < 2; q++) {
        int idx = q * 256 + tid;           // 0..511 linear float4
        float4 v = gm[idx];
        gm[idx] = make_float4(0.f, 0.f, 0.f, 0.f);
        ((float4*)m_sm)[idx] = make_float4(v.x * 0.125f, v.y * 0.125f,
                                           v.z * 0.125f, v.w * 0.125f);
    }
    if (tid < NGRAPH) bins[tid] = 0.0f;
    __syncthreads();

    int w = tid >> 5, g = tid & 31;
    int g2 = g * 2;

#pragma unroll
    for (int pair = 0; pair < 2; pair++) {
        int nl0 = w * 4 + pair * 2;
        const float* m0 = m_sm + nl0 * CDIM;
        const float* m1 = m0 + CDIM;
        unsigned long long acc0 = 0ull, acc1 = 0ull;
#pragma unroll 16
        for (int c = 0; c < CDIM; c++) {
            unsigned long long wv =
                *(const unsigned long long*)(swl + c * CDIM + g2);
            float av = m0[c], bv = m1[c];
            acc0 = ffma2(pack2(av, av), wv, acc0);
            acc1 = ffma2(pack2(bv, bv), wv, acc1);
        }
#pragma unroll
        for (int e = 0; e < 2; e++) {
            int node = blockIdx.x * NPB + nl0 + e;
            float2 f = unpack2(e ? acc1 : acc0);
            int el = g_elem[node];
            float2 w0 = *(const float2*)(Wprod + (0 * NELEM + el) * CDIM + g2);
            float2 w1 = *(const float2*)(Wprod + (1 * NELEM + el) * CDIM + g2);
            float2 w2 = *(const float2*)(Wprod + (2 * NELEM + el) * CDIM + g2);
            float2 sc = *(const float2*)(Wsc + el * CDIM + g2);
            float2 wr = *(const float2*)(Wread + g2);
            float2 sp = *(const float2*)(g_s + node * CDIM + g2);
            float hx = f.x * (w0.x + w1.x * f.x + w2.x * f.x * f.x) + sc.x * sp.x;
            float hy = f.y * (w0.y + w1.y * f.y + w2.y * f.y * f.y) + sc.y * sp.y;
            *(float2*)(g_s + node * CDIM + g2) = make_float2(hx, hy);
            float en = hx * wr.x + hy * wr.y;
#pragma unroll
            for (int off = 16; off > 0; off >>= 1)
                en += __shfl_down_sync(0xffffffffu, en, off);
            if (g == 0) {
                if (!last) g_energy[node] += en;
                else atomicAdd(&bins[batch[node]], g_energy[node] + en);
            }
        }
    }
    if (last) {
        __syncthreads();
        if (tid < NGRAPH) atomicAdd(d_out + tid, bins[tid]);
    }
}

// ---------------------------------------------------------------------------
extern "C" void kernel_launch(void* const* d_in, const int* in_sizes, int n_in,
                              void* d_out, int out_size) {
    const float* positions       = (const float*)d_in[0];
    const float* node_attrs      = (const float*)d_in[1];
    const int*   edge_index      = (const int*)d_in[2];
    const int*   batch           = (const int*)d_in[3];
    const float* atomic_energies = (const float*)d_in[4];
    const float* W_embed         = (const float*)d_in[5];
    const float* rw1             = (const float*)d_in[6];
    const float* rb1             = (const float*)d_in[7];
    const float* rw2             = (const float*)d_in[8];
    const float* rb2             = (const float*)d_in[9];
    const float* rw3             = (const float*)d_in[10];
    const float* Wlin            = (const float*)d_in[11];
    const float* Wprod           = (const float*)d_in[12];
    const float* Wsc             = (const float*)d_in[13];
    const float* Wread           = (const float*)d_in[14];
    float* out = (float*)d_out;

    const int EDGE_SMEM = 17024 * 4;   // 68096 B dynamic
    cudaFuncSetAttribute(edge_mlp_kernel,
                         cudaFuncAttributeMaxDynamicSharedMemorySize, EDGE_SMEM);

    init_kernel<<<N_NODES / 128, 128>>>(node_attrs, atomic_energies, W_embed, out);
    for (int i = 0; i < 2; i++) {
        edge_mlp_kernel<<<N_EDGES / EPB, 256, EDGE_SMEM>>>(
            rw1 + i * NB * CDIM, rb1 + i * CDIM,
            rw2 + i * CDIM * CDIM, rb2 + i * CDIM,
            rw3 + i * CDIM * 4 * CDIM, edge_index, positions, i == 0 ? 1 : 0);
        node_kernel<<<N_NODES / NPB, 256>>>(
            Wlin + i * 4 * CDIM * CDIM,
            Wprod + i * 3 * NELEM * CDIM,
            Wsc + i * NELEM * CDIM,
            Wread + i * CDIM,
            batch, out, i == 1 ? 1 : 0);
    }
}